// round 12
// baseline (speedup 1.0000x reference)
#include <cuda_runtime.h>
#include <cuda_fp16.h>
#include <cstdint>
#include <math.h>

#define Bn 32
#define Cn 128
#define Hn 56
#define Wn 56
#define HW 3136
#define CEn 512
#define EPSV 1e-6f

__device__ float g_pooled[Bn * Cn];
__device__ float g_dyn[Bn * Cn * 25];
__device__ __half g_conv[(size_t)Bn * Cn * HW];    // fp16
__device__ __half g_gelu[(size_t)Bn * HW * CEn];   // [b][p][ce] fp16
__device__ float g_sumsq[Bn * CEn];
__device__ float g_scale[Bn * CEn];
__device__ uint32_t g_wea[32768];   // expand W fp16x2 [512][64]
__device__ uint32_t g_wsa[32768];   // shrink W fp16x2 [128][256]

// ---------- helpers ----------
__device__ __forceinline__ uint32_t smem_u32(const void* p) {
    uint32_t a;
    asm("{ .reg .u64 t; cvta.to.shared.u64 t, %1; cvt.u32.u64 %0, t; }" : "=r"(a) : "l"(p));
    return a;
}
__device__ __forceinline__ void ldm4(uint32_t* r, uint32_t a) {
    asm volatile("ldmatrix.sync.aligned.m8n8.x4.shared.b16 {%0,%1,%2,%3}, [%4];"
        : "=r"(r[0]), "=r"(r[1]), "=r"(r[2]), "=r"(r[3]) : "r"(a));
}
__device__ __forceinline__ void mma_f16(float* c, const uint32_t* a, const uint32_t* b) {
    asm volatile("mma.sync.aligned.m16n8k16.row.col.f32.f16.f16.f32 "
        "{%0,%1,%2,%3},{%4,%5,%6,%7},{%8,%9},{%0,%1,%2,%3};"
        : "+f"(c[0]), "+f"(c[1]), "+f"(c[2]), "+f"(c[3])
        : "r"(a[0]), "r"(a[1]), "r"(a[2]), "r"(a[3]), "r"(b[0]), "r"(b[1]));
}
__device__ __forceinline__ uint32_t pkh2(float a, float b) {
    __half2 h = __floats2half2_rn(a, b);
    return *(uint32_t*)&h;
}
// Abramowitz-Stegun 7.1.26 erf approximation (abs err <= 1.5e-7)
__device__ __forceinline__ float gelu_f(float v) {
    float z = fabsf(v) * 0.7071067811865476f;
    float t = __fdividef(1.f, fmaf(0.3275911f, z, 1.f));
    float p = t * fmaf(t, fmaf(t, fmaf(t, fmaf(t, 1.061405429f, -1.453152027f),
                1.421413741f), -0.284496736f), 0.254829592f);
    float erfv = 1.f - p * __expf(-z * z);
    erfv = copysignf(erfv, v);
    return 0.5f * v * (1.f + erfv);
}

// ---------- merged: weight preconversion + sumsq zero + global avg pool ----------
__global__ void k_prep(const float* __restrict__ we, const float* __restrict__ ws,
                       const float* __restrict__ x) {
    if (blockIdx.x < 256) {
        int g = blockIdx.x * 256 + threadIdx.x;         // 65536
        if (g < Bn * CEn) g_sumsq[g] = 0.f;
        int which = g >> 15, r = g & 32767;
        int shift = which ? 8 : 6;
        const float* src = which ? ws : we;
        int kp = r & ((1 << shift) - 1), row = r >> shift;
        const float* s = src + (size_t)row * (2 << shift) + 2 * kp;
        (which ? g_wsa : g_wea)[(row << shift) + kp] = pkh2(s[0], s[1]);
        return;
    }
    int bc = blockIdx.x - 256;
    const float* p = x + (size_t)bc * HW;
    int t = threadIdx.x, lane = t & 31, wid = t >> 5;
    float s = 0.f;
    for (int i = t; i < HW / 4; i += 256) {
        float4 v = reinterpret_cast<const float4*>(p)[i];
        s += v.x + v.y + v.z + v.w;
    }
    #pragma unroll
    for (int o = 16; o > 0; o >>= 1) s += __shfl_xor_sync(~0u, s, o);
    __shared__ float sm[8];
    if (lane == 0) sm[wid] = s;
    __syncthreads();
    if (t == 0) {
        float a = 0.f;
        #pragma unroll
        for (int i = 0; i < 8; i++) a += sm[i];
        g_pooled[bc] = a * (1.f / (float)HW);
    }
}

// fc1+LN1 (warp 0, redundant per block) then fc2
__global__ void k_fc(const float* __restrict__ w_fc1, const float* __restrict__ ln1w,
                     const float* __restrict__ ln1b, const float* __restrict__ w_fc2) {
    int b = blockIdx.y, t = threadIdx.x;
    __shared__ float sh[32];
    if (t < 32) {
        const float* sp = g_pooled + b * Cn;
        const float* wr = w_fc1 + t * Cn;
        float a = 0.f;
        #pragma unroll
        for (int i = 0; i < Cn; i++) a += wr[i] * sp[i];
        float u = a;
        #pragma unroll
        for (int o = 16; o > 0; o >>= 1) u += __shfl_xor_sync(~0u, u, o);
        u *= (1.f / 32.f);
        float d = a - u, v = d * d;
        #pragma unroll
        for (int o = 16; o > 0; o >>= 1) v += __shfl_xor_sync(~0u, v, o);
        v *= (1.f / 32.f);
        sh[t] = d * rsqrtf(v + EPSV) * ln1w[t] + ln1b[t];
    }
    __syncthreads();
    int i = blockIdx.x * 256 + t;
    if (i < Cn * 25) {
        const float* wr = w_fc2 + i * 32;
        float a = 0.f;
        #pragma unroll
        for (int j = 0; j < 32; j++) a += wr[j] * sh[j];
        g_dyn[b * Cn * 25 + i] = a;
    }
}

// ---------- conv: 8 px/thread, aligned vector smem, zero-pass fill ----------
__global__ void __launch_bounds__(256) k_conv(const float* __restrict__ x) {
    int bc = blockIdx.x;
    __shared__ float tile[60 * 64];   // interior at [(r+2)*64 + (c+2)]
    int t = threadIdx.x;
    // zero whole tile (960 STS.128)
    #pragma unroll
    for (int i = 0; i < 4; i++) {
        int idx = t + i * 256;
        if (idx < 960) ((float4*)tile)[idx] = make_float4(0.f, 0.f, 0.f, 0.f);
    }
    float kk[25];
    const float* dp = g_dyn + bc * 25;
    #pragma unroll
    for (int i = 0; i < 25; i++) kk[i] = dp[i];
    __syncthreads();
    // interior fill: 784 float4 rows of x, 2x STS.64 each (col offset +2)
    const float* xp = x + (size_t)bc * HW;
    #pragma unroll
    for (int i = 0; i < 4; i++) {
        int idx = t + i * 256;
        if (idx < 784) {
            int r = idx / 14, c4 = (idx % 14) * 4;
            float4 v = *(const float4*)&xp[r * 56 + c4];
            float* d = &tile[(r + 2) * 64 + c4 + 2];
            *(float2*)d = make_float2(v.x, v.y);
            *(float2*)(d + 2) = make_float2(v.z, v.w);
        }
    }
    __syncthreads();
    __half* op = g_conv + (size_t)bc * HW;
    // 392 octets: h = q/7, w0 = (q%7)*8
    for (int q = t; q < 392; q += 256) {
        int h = q / 7, w0 = (q % 7) * 8;
        float a0=0.f,a1=0.f,a2=0.f,a3=0.f,a4=0.f,a5=0.f,a6=0.f,a7=0.f;
        #pragma unroll
        for (int i = 0; i < 5; i++) {
            const float* rp = &tile[(h + i) * 64 + w0];
            float4 u0 = *(const float4*)rp;
            float4 u1 = *(const float4*)(rp + 4);
            float4 u2 = *(const float4*)(rp + 8);
            float r_[12] = {u0.x,u0.y,u0.z,u0.w,u1.x,u1.y,u1.z,u1.w,u2.x,u2.y,u2.z,u2.w};
            #pragma unroll
            for (int j = 0; j < 5; j++) {
                float kv = kk[i * 5 + j];
                a0 = fmaf(kv, r_[j],     a0);
                a1 = fmaf(kv, r_[j + 1], a1);
                a2 = fmaf(kv, r_[j + 2], a2);
                a3 = fmaf(kv, r_[j + 3], a3);
                a4 = fmaf(kv, r_[j + 4], a4);
                a5 = fmaf(kv, r_[j + 5], a5);
                a6 = fmaf(kv, r_[j + 6], a6);
                a7 = fmaf(kv, r_[j + 7], a7);
            }
        }
        uint4 o;
        o.x = pkh2(a0, a1); o.y = pkh2(a2, a3);
        o.z = pkh2(a4, a5); o.w = pkh2(a6, a7);
        *(uint4*)&op[h * 56 + w0] = o;
    }
}

// ---------- expand: LN2 + fp16 mma GEMM + gelu + GRN sumsq ----------
#define E_RB 30720
#define E_SMEM 69760
__global__ void __launch_bounds__(256, 2)
k_expand(const float* __restrict__ ln2w, const float* __restrict__ ln2b) {
    extern __shared__ char sb[];
    uint32_t sbu = smem_u32(sb);
    int t = threadIdx.x, wid = t >> 5, lane = t & 31;
    int b = blockIdx.y, p0 = blockIdx.x * 112;
    float* s_lnw = (float*)(sb + 65536);
    float* s_lnb = (float*)(sb + 66048);
    float* r1 = (float*)(sb + 66560);
    float* r2 = (float*)(sb + 67456);
    float* smu = (float*)(sb + 68352);
    float* srs = (float*)(sb + 68800);
    float* s_sq = (float*)(sb + 69248);
    if (t < 128) { s_lnw[t] = ln2w[t]; s_lnb[t] = ln2b[t]; }
    const __half* cp = g_conv + (size_t)b * Cn * HW + p0;
    #pragma unroll
    for (int i = 0; i < 7; i++) {
        int idx = t + i * 256;
        int c = idx / 14, qq = idx % 14;
        uint4 v = *(const uint4*)&cp[(size_t)c * HW + qq * 8];
        uint32_t* d = (uint32_t*)(sb + E_RB + c * 260 + qq * 16);
        d[0] = v.x; d[1] = v.y; d[2] = v.z; d[3] = v.w;
    }
    __syncthreads();
    if (t < 224) {
        int p = t % 112, h = t / 112;
        float s = 0.f, s2 = 0.f;
        for (int c = h * 64; c < h * 64 + 64; c++) {
            float v = __half2float(*(__half*)(sb + E_RB + c * 260 + 2 * p));
            s += v; s2 += v * v;
        }
        r1[t] = s; r2[t] = s2;
    }
    __syncthreads();
    if (t < 112) {
        float s = r1[t] + r1[112 + t], s2 = r2[t] + r2[112 + t];
        float mu = s * (1.f / 128.f);
        smu[t] = mu;
        srs[t] = rsqrtf(s2 * (1.f / 128.f) - mu * mu + EPSV);
    }
    __syncthreads();
    #pragma unroll
    for (int i = 0; i < 28; i++) {
        int idx = t + i * 256, p = idx >> 6, cp2 = idx & 63, c0 = cp2 * 2;
        float mu = smu[p], rs = srs[p];
        float x0 = __half2float(*(__half*)(sb + E_RB + c0 * 260 + 2 * p));
        float x1 = __half2float(*(__half*)(sb + E_RB + (c0 + 1) * 260 + 2 * p));
        float v0 = (x0 - mu) * rs * s_lnw[c0] + s_lnb[c0];
        float v1 = (x1 - mu) * rs * s_lnw[c0 + 1] + s_lnb[c0 + 1];
        *(uint32_t*)(sb + p * 272 + cp2 * 4) = pkh2(v0, v1);
    }
    __syncthreads();
    uint32_t aA = sbu + E_RB + (wid * 16 + (lane & 15)) * 272 + (lane >> 4) * 16;
    uint32_t aB = sbu + ((lane & 7) + ((lane >> 4) & 1) * 8) * 272 + ((lane >> 3) & 1) * 16;
    int r0 = wid * 16 + (lane >> 2), cbase = (lane & 3) * 2;
    uint32_t* gbase = (uint32_t*)g_gelu + ((size_t)b * HW + p0) * 256;
    for (int m = 0; m < 4; m++) {
        if (t < 128) s_sq[t] = 0.f;
        const uint4* s0 = (const uint4*)g_wea;
        #pragma unroll
        for (int i = 0; i < 8; i++) {
            int idx = t + i * 256;
            int r = idx >> 4, q = idx & 15;
            uint4 v = s0[(m * 128 + r) * 16 + q];
            *(uint4*)(sb + E_RB + r * 272 + q * 16) = v;
        }
        __syncthreads();
        float acc[14][4];
        #pragma unroll
        for (int n = 0; n < 14; n++) { acc[n][0] = acc[n][1] = acc[n][2] = acc[n][3] = 0.f; }
        #pragma unroll
        for (int k = 0; k < 8; k++) {
            uint32_t ah[4];
            ldm4(ah, aA + k * 32);
            #pragma unroll
            for (int np = 0; np < 7; np++) {
                uint32_t bh[4];
                ldm4(bh, aB + np * 4352 + k * 32);
                mma_f16(acc[2 * np], ah, bh);
                mma_f16(acc[2 * np + 1], ah, bh + 2);
            }
        }
        __syncthreads();
        float ss0 = 0.f, ss1 = 0.f;
        #pragma unroll
        for (int n = 0; n < 14; n++) {
            int cc = n * 8 + cbase;
            float g0 = gelu_f(acc[n][0]), g1 = gelu_f(acc[n][1]);
            float g2 = gelu_f(acc[n][2]), g3 = gelu_f(acc[n][3]);
            ss0 += g0 * g0 + g1 * g1;
            ss1 += g2 * g2 + g3 * g3;
            *(__half*)(sb + E_RB + cc * 264 + 2 * r0) = __float2half_rn(g0);
            *(__half*)(sb + E_RB + (cc + 1) * 264 + 2 * r0) = __float2half_rn(g1);
            *(__half*)(sb + E_RB + cc * 264 + 2 * (r0 + 8)) = __float2half_rn(g2);
            *(__half*)(sb + E_RB + (cc + 1) * 264 + 2 * (r0 + 8)) = __float2half_rn(g3);
        }
        atomicAdd(&s_sq[r0], ss0);
        atomicAdd(&s_sq[r0 + 8], ss1);
        __syncthreads();
        if (t < 128) atomicAdd(&g_sumsq[b * CEn + m * 128 + t], s_sq[t]);
        #pragma unroll
        for (int i = 0; i < 28; i++) {
            int idx = t + i * 256;
            int px = idx >> 6, w = idx & 63;
            uint32_t v = *(uint32_t*)(sb + E_RB + px * 264 + w * 4);
            gbase[(size_t)px * 256 + m * 64 + w] = v;
        }
        __syncthreads();
    }
}

__global__ void k_grn(const float* __restrict__ gamma) {
    int b = blockIdx.x, t = threadIdx.x;
    float gx = sqrtf(g_sumsq[b * CEn + t]);
    __shared__ float sm[CEn];
    sm[t] = gx;
    __syncthreads();
    for (int o = 256; o > 0; o >>= 1) {
        if (t < o) sm[t] += sm[t + o];
        __syncthreads();
    }
    g_scale[b * CEn + t] = gamma[t] * (gx / (sm[0] * (1.f / (float)CEn) + EPSV)) + 1.f;
}

// ---------- shrink: fp16 mma GEMM (scale/beta folded) + residual ----------
#define S_SMEM 52224
__global__ void __launch_bounds__(256, 3)
k_shrink(const float* __restrict__ beta, const float* __restrict__ x, float* __restrict__ out) {
    extern __shared__ char sb[];
    uint32_t sbu = smem_u32(sb);
    int t = threadIdx.x, wid = t >> 5, lane = t & 31;
    int b = blockIdx.y, p0 = blockIdx.x * 64;
    const __half* gz = g_gelu + ((size_t)b * HW + p0) * CEn;
    float acc[8][4];
    #pragma unroll
    for (int n = 0; n < 8; n++) acc[n][0] = acc[n][1] = acc[n][2] = acc[n][3] = 0.f;
    uint32_t aA = sbu + 17408 + (wid * 16 + (lane & 15)) * 272 + (lane >> 4) * 16;
    uint32_t aB = sbu + ((lane & 7) + ((lane >> 4) & 1) * 8) * 272 + ((lane >> 3) & 1) * 16;
    for (int kt = 0; kt < 4; kt++) {
        __syncthreads();
        const uint4* s0 = (const uint4*)g_wsa;
        #pragma unroll
        for (int i = 0; i < 8; i++) {
            int idx = t + i * 256;
            int r = idx >> 4, q = idx & 15;
            uint4 v = s0[r * 64 + kt * 16 + q];
            *(uint4*)(sb + 17408 + r * 272 + q * 16) = v;
        }
        #pragma unroll
        for (int i = 0; i < 8; i++) {
            int idx = t + i * 256;
            int p = idx >> 5, q = idx & 31;
            int ce = kt * 128 + q * 4;
            uint2 raw = *(const uint2*)&gz[(size_t)p * CEn + ce];
            __half2 g01 = *(__half2*)&raw.x, g23 = *(__half2*)&raw.y;
            float4 a = *(const float4*)&g_scale[b * CEn + ce];
            float4 bt = *(const float4*)&beta[ce];
            float z0 = a.x * __low2float(g01) + bt.x;
            float z1 = a.y * __high2float(g01) + bt.y;
            float z2 = a.z * __low2float(g23) + bt.z;
            float z3 = a.w * __high2float(g23) + bt.w;
            *(uint2*)(sb + p * 272 + q * 8) = make_uint2(pkh2(z0, z1), pkh2(z2, z3));
        }
        __syncthreads();
        #pragma unroll
        for (int k = 0; k < 8; k++) {
            uint32_t ah[4];
            ldm4(ah, aA + k * 32);
            #pragma unroll
            for (int np = 0; np < 4; np++) {
                uint32_t bh[4];
                ldm4(bh, aB + np * 4352 + k * 32);
                mma_f16(acc[2 * np], ah, bh);
                mma_f16(acc[2 * np + 1], ah, bh + 2);
            }
        }
    }
    __syncthreads();
    float* s_out = (float*)sb;   // [128][68]
    int r0 = wid * 16 + (lane >> 2), cbase = (lane & 3) * 2;
    #pragma unroll
    for (int n = 0; n < 8; n++) {
        int cc = n * 8 + cbase;
        s_out[r0 * 68 + cc] = acc[n][0];
        s_out[r0 * 68 + cc + 1] = acc[n][1];
        s_out[(r0 + 8) * 68 + cc] = acc[n][2];
        s_out[(r0 + 8) * 68 + cc + 1] = acc[n][3];
    }
    __syncthreads();
    const float* xp = x + (size_t)b * Cn * HW + p0;
    float* op = out + (size_t)b * Cn * HW + p0;
    #pragma unroll
    for (int i = 0; i < 8; i++) {
        int idx = t + i * 256, oc = idx >> 4, p4 = (idx & 15) * 4;
        float4 v = *(float4*)&s_out[oc * 68 + p4];
        float4 xv = *(const float4*)&xp[(size_t)oc * HW + p4];
        v.x += xv.x; v.y += xv.y; v.z += xv.z; v.w += xv.w;
        *(float4*)&op[(size_t)oc * HW + p4] = v;
    }
}

// ---------- launch ----------
extern "C" void kernel_launch(void* const* d_in, const int* in_sizes, int n_in,
                              void* d_out, int out_size) {
    const float* x        = (const float*)d_in[0];
    const float* w_fc1    = (const float*)d_in[1];
    const float* ln1_w    = (const float*)d_in[2];
    const float* ln1_b    = (const float*)d_in[3];
    const float* w_fc2    = (const float*)d_in[4];
    const float* ln2_w    = (const float*)d_in[5];
    const float* ln2_b    = (const float*)d_in[6];
    const float* w_expand = (const float*)d_in[7];
    const float* w_shrink = (const float*)d_in[8];
    const float* grn_g    = (const float*)d_in[9];
    const float* grn_b    = (const float*)d_in[10];
    float* out = (float*)d_out;

    cudaFuncSetAttribute(k_expand, cudaFuncAttributeMaxDynamicSharedMemorySize, E_SMEM);
    cudaFuncSetAttribute(k_shrink, cudaFuncAttributeMaxDynamicSharedMemorySize, S_SMEM);

    k_prep<<<256 + Bn * Cn, 256>>>(w_expand, w_shrink, x);
    k_fc<<<dim3(13, Bn), 256>>>(w_fc1, ln1_w, ln1_b, w_fc2);
    k_conv<<<Bn * Cn, 256>>>(x);
    k_expand<<<dim3(28, Bn), 256, E_SMEM>>>(ln2_w, ln2_b);
    k_grn<<<Bn, CEn>>>(grn_g);
    k_shrink<<<dim3(49, Bn), 256, S_SMEM>>>(grn_b, x, out);
}

// round 13
// speedup vs baseline: 1.3414x; 1.3414x over previous
#include <cuda_runtime.h>
#include <cuda_fp16.h>
#include <cstdint>
#include <math.h>

#define Bn 32
#define Cn 128
#define Hn 56
#define Wn 56
#define HW 3136
#define CEn 512
#define EPSV 1e-6f

__device__ float g_pooled[Bn * Cn];
__device__ float g_dyn[Bn * Cn * 25];
__device__ __half g_conv[(size_t)Bn * Cn * HW];    // fp16
__device__ __half g_gelu[(size_t)Bn * HW * CEn];   // [b][p][ce] fp16
__device__ float g_sumsq[Bn * CEn];
__device__ float g_scale[Bn * CEn];
__device__ uint32_t g_wea[32768];   // expand W fp16x2 [512][64]
__device__ uint32_t g_wsa[32768];   // shrink W fp16x2 [128][256]

// ---------- helpers ----------
__device__ __forceinline__ uint32_t smem_u32(const void* p) {
    uint32_t a;
    asm("{ .reg .u64 t; cvta.to.shared.u64 t, %1; cvt.u32.u64 %0, t; }" : "=r"(a) : "l"(p));
    return a;
}
__device__ __forceinline__ void ldm4(uint32_t* r, uint32_t a) {
    asm volatile("ldmatrix.sync.aligned.m8n8.x4.shared.b16 {%0,%1,%2,%3}, [%4];"
        : "=r"(r[0]), "=r"(r[1]), "=r"(r[2]), "=r"(r[3]) : "r"(a));
}
__device__ __forceinline__ void mma_f16(float* c, const uint32_t* a, const uint32_t* b) {
    asm volatile("mma.sync.aligned.m16n8k16.row.col.f32.f16.f16.f32 "
        "{%0,%1,%2,%3},{%4,%5,%6,%7},{%8,%9},{%0,%1,%2,%3};"
        : "+f"(c[0]), "+f"(c[1]), "+f"(c[2]), "+f"(c[3])
        : "r"(a[0]), "r"(a[1]), "r"(a[2]), "r"(a[3]), "r"(b[0]), "r"(b[1]));
}
__device__ __forceinline__ uint32_t pkh2(float a, float b) {
    __half2 h = __floats2half2_rn(a, b);
    return *(uint32_t*)&h;
}
// Abramowitz-Stegun 7.1.26 erf approximation (abs err <= 1.5e-7)
__device__ __forceinline__ float gelu_f(float v) {
    float z = fabsf(v) * 0.7071067811865476f;
    float t = __fdividef(1.f, fmaf(0.3275911f, z, 1.f));
    float p = t * fmaf(t, fmaf(t, fmaf(t, fmaf(t, 1.061405429f, -1.453152027f),
                1.421413741f), -0.284496736f), 0.254829592f);
    float erfv = 1.f - p * __expf(-z * z);
    erfv = copysignf(erfv, v);
    return 0.5f * v * (1.f + erfv);
}

// ---------- weight preconversion (+ sumsq zero), single launch ----------
__global__ void k_wprep(const float* __restrict__ we, const float* __restrict__ ws) {
    int g = blockIdx.x * 256 + threadIdx.x;         // 65536
    if (g < Bn * CEn) g_sumsq[g] = 0.f;
    int which = g >> 15, r = g & 32767;
    int shift = which ? 8 : 6;
    const float* src = which ? ws : we;
    int kp = r & ((1 << shift) - 1), row = r >> shift;
    const float* s = src + (size_t)row * (2 << shift) + 2 * kp;
    (which ? g_wsa : g_wea)[(row << shift) + kp] = pkh2(s[0], s[1]);
}

// ---------- small kernels ----------
__global__ void k_pool(const float* __restrict__ x) {
    int bc = blockIdx.x;
    const float* p = x + (size_t)bc * HW;
    int t = threadIdx.x, lane = t & 31, wid = t >> 5;
    float s = 0.f;
    for (int i = t; i < HW / 4; i += 256) {
        float4 v = reinterpret_cast<const float4*>(p)[i];
        s += v.x + v.y + v.z + v.w;
    }
    #pragma unroll
    for (int o = 16; o > 0; o >>= 1) s += __shfl_xor_sync(~0u, s, o);
    __shared__ float sm[8];
    if (lane == 0) sm[wid] = s;
    __syncthreads();
    if (t == 0) {
        float a = 0.f;
        #pragma unroll
        for (int i = 0; i < 8; i++) a += sm[i];
        g_pooled[bc] = a * (1.f / (float)HW);
    }
}

// fc1+LN1 (warp 0, redundant per block) then fc2
__global__ void k_fc(const float* __restrict__ w_fc1, const float* __restrict__ ln1w,
                     const float* __restrict__ ln1b, const float* __restrict__ w_fc2) {
    int b = blockIdx.y, t = threadIdx.x;
    __shared__ float sh[32];
    if (t < 32) {
        const float* sp = g_pooled + b * Cn;
        const float* wr = w_fc1 + t * Cn;
        float a = 0.f;
        #pragma unroll
        for (int i = 0; i < Cn; i++) a += wr[i] * sp[i];
        float u = a;
        #pragma unroll
        for (int o = 16; o > 0; o >>= 1) u += __shfl_xor_sync(~0u, u, o);
        u *= (1.f / 32.f);
        float d = a - u, v = d * d;
        #pragma unroll
        for (int o = 16; o > 0; o >>= 1) v += __shfl_xor_sync(~0u, v, o);
        v *= (1.f / 32.f);
        sh[t] = d * rsqrtf(v + EPSV) * ln1w[t] + ln1b[t];
    }
    __syncthreads();
    int i = blockIdx.x * 256 + t;
    if (i < Cn * 25) {
        const float* wr = w_fc2 + i * 32;
        float a = 0.f;
        #pragma unroll
        for (int j = 0; j < 32; j++) a += wr[j] * sh[j];
        g_dyn[b * Cn * 25 + i] = a;
    }
}

__global__ void k_conv(const float* __restrict__ x) {
    int bc = blockIdx.x;
    __shared__ float tile[60 * 60];
    const float* xp = x + (size_t)bc * HW;
    for (int i = threadIdx.x; i < 3600; i += 256) {
        int r = i / 60, cc = i % 60, h = r - 2, w = cc - 2;
        tile[i] = (h >= 0 && h < Hn && w >= 0 && w < Wn) ? xp[h * Wn + w] : 0.f;
    }
    float kk[25];
    const float* dp = g_dyn + bc * 25;
    #pragma unroll
    for (int i = 0; i < 25; i++) kk[i] = dp[i];
    __syncthreads();
    __half* op = g_conv + (size_t)bc * HW;
    for (int q = threadIdx.x; q < 784; q += 256) {
        int h = q / 14, w0 = (q % 14) * 4;
        float a0 = 0.f, a1 = 0.f, a2 = 0.f, a3 = 0.f;
        #pragma unroll
        for (int i = 0; i < 5; i++) {
            const float* r = &tile[(h + i) * 60 + w0];
            float r0 = r[0], r1 = r[1], r2 = r[2], r3 = r[3];
            float r4 = r[4], r5 = r[5], r6 = r[6], r7 = r[7];
            float k0 = kk[i * 5], k1 = kk[i * 5 + 1], k2 = kk[i * 5 + 2];
            float k3 = kk[i * 5 + 3], k4 = kk[i * 5 + 4];
            a0 += k0 * r0 + k1 * r1 + k2 * r2 + k3 * r3 + k4 * r4;
            a1 += k0 * r1 + k1 * r2 + k2 * r3 + k3 * r4 + k4 * r5;
            a2 += k0 * r2 + k1 * r3 + k2 * r4 + k3 * r5 + k4 * r6;
            a3 += k0 * r3 + k1 * r4 + k2 * r5 + k3 * r6 + k4 * r7;
        }
        *reinterpret_cast<uint2*>(&op[q * 4]) = make_uint2(pkh2(a0, a1), pkh2(a2, a3));
    }
}

// ---------- expand: LN2 + fp16 mma GEMM + gelu + GRN sumsq ----------
#define E_RB 30720
#define E_SMEM 69760
__global__ void __launch_bounds__(256, 2)
k_expand(const float* __restrict__ ln2w, const float* __restrict__ ln2b) {
    extern __shared__ char sb[];
    uint32_t sbu = smem_u32(sb);
    int t = threadIdx.x, wid = t >> 5, lane = t & 31;
    int b = blockIdx.y, p0 = blockIdx.x * 112;
    float* s_lnw = (float*)(sb + 65536);
    float* s_lnb = (float*)(sb + 66048);
    float* r1 = (float*)(sb + 66560);
    float* r2 = (float*)(sb + 67456);
    float* smu = (float*)(sb + 68352);
    float* srs = (float*)(sb + 68800);
    float* s_sq = (float*)(sb + 69248);
    if (t < 128) { s_lnw[t] = ln2w[t]; s_lnb[t] = ln2b[t]; }
    const __half* cp = g_conv + (size_t)b * Cn * HW + p0;
    #pragma unroll
    for (int i = 0; i < 7; i++) {
        int idx = t + i * 256;
        int c = idx / 14, qq = idx % 14;
        uint4 v = *(const uint4*)&cp[(size_t)c * HW + qq * 8];
        uint32_t* d = (uint32_t*)(sb + E_RB + c * 260 + qq * 16);
        d[0] = v.x; d[1] = v.y; d[2] = v.z; d[3] = v.w;
    }
    __syncthreads();
    if (t < 224) {
        int p = t % 112, h = t / 112;
        float s = 0.f, s2 = 0.f;
        for (int c = h * 64; c < h * 64 + 64; c++) {
            float v = __half2float(*(__half*)(sb + E_RB + c * 260 + 2 * p));
            s += v; s2 += v * v;
        }
        r1[t] = s; r2[t] = s2;
    }
    __syncthreads();
    if (t < 112) {
        float s = r1[t] + r1[112 + t], s2 = r2[t] + r2[112 + t];
        float mu = s * (1.f / 128.f);
        smu[t] = mu;
        srs[t] = rsqrtf(s2 * (1.f / 128.f) - mu * mu + EPSV);
    }
    __syncthreads();
    #pragma unroll
    for (int i = 0; i < 28; i++) {
        int idx = t + i * 256, p = idx >> 6, cp2 = idx & 63, c0 = cp2 * 2;
        float mu = smu[p], rs = srs[p];
        float x0 = __half2float(*(__half*)(sb + E_RB + c0 * 260 + 2 * p));
        float x1 = __half2float(*(__half*)(sb + E_RB + (c0 + 1) * 260 + 2 * p));
        float v0 = (x0 - mu) * rs * s_lnw[c0] + s_lnb[c0];
        float v1 = (x1 - mu) * rs * s_lnw[c0 + 1] + s_lnb[c0 + 1];
        *(uint32_t*)(sb + p * 272 + cp2 * 4) = pkh2(v0, v1);
    }
    __syncthreads();
    uint32_t aA = sbu + E_RB + (wid * 16 + (lane & 15)) * 272 + (lane >> 4) * 16;
    uint32_t aB = sbu + ((lane & 7) + ((lane >> 4) & 1) * 8) * 272 + ((lane >> 3) & 1) * 16;
    int r0 = wid * 16 + (lane >> 2), cbase = (lane & 3) * 2;
    uint2* gbase = (uint2*)g_gelu + ((size_t)b * HW + p0) * 128;
    for (int m = 0; m < 4; m++) {
        if (t < 128) s_sq[t] = 0.f;
        const uint4* s0 = (const uint4*)g_wea;
        #pragma unroll
        for (int i = 0; i < 8; i++) {
            int idx = t + i * 256;
            int r = idx >> 4, q = idx & 15;
            uint4 v = s0[(m * 128 + r) * 16 + q];
            *(uint4*)(sb + E_RB + r * 272 + q * 16) = v;
        }
        __syncthreads();
        float acc[14][4];
        #pragma unroll
        for (int n = 0; n < 14; n++) { acc[n][0] = acc[n][1] = acc[n][2] = acc[n][3] = 0.f; }
        #pragma unroll
        for (int k = 0; k < 8; k++) {
            uint32_t ah[4];
            ldm4(ah, aA + k * 32);
            #pragma unroll
            for (int np = 0; np < 7; np++) {
                uint32_t bh[4];
                ldm4(bh, aB + np * 4352 + k * 32);
                mma_f16(acc[2 * np], ah, bh);
                mma_f16(acc[2 * np + 1], ah, bh + 2);
            }
        }
        __syncthreads();      // A dead; region B becomes gout [px][oc] stride 264B
        float ss0 = 0.f, ss1 = 0.f;
        #pragma unroll
        for (int n = 0; n < 14; n++) {
            int cc = n * 8 + cbase;           // pixel index
            float g0 = gelu_f(acc[n][0]), g1 = gelu_f(acc[n][1]);
            float g2 = gelu_f(acc[n][2]), g3 = gelu_f(acc[n][3]);
            ss0 += g0 * g0 + g1 * g1;
            ss1 += g2 * g2 + g3 * g3;
            *(__half*)(sb + E_RB + cc * 264 + 2 * r0) = __float2half_rn(g0);
            *(__half*)(sb + E_RB + (cc + 1) * 264 + 2 * r0) = __float2half_rn(g1);
            *(__half*)(sb + E_RB + cc * 264 + 2 * (r0 + 8)) = __float2half_rn(g2);
            *(__half*)(sb + E_RB + (cc + 1) * 264 + 2 * (r0 + 8)) = __float2half_rn(g3);
        }
        atomicAdd(&s_sq[r0], ss0);
        atomicAdd(&s_sq[r0 + 8], ss1);
        __syncthreads();
        if (t < 128) atomicAdd(&g_sumsq[b * CEn + m * 128 + t], s_sq[t]);
        // store pass: uint2 (8B) wide, coalesced
        #pragma unroll
        for (int i = 0; i < 14; i++) {
            int idx = t + i * 256;                 // 3584 uint2
            int px = idx >> 5, w2 = idx & 31;
            uint2 v = *(uint2*)(sb + E_RB + px * 264 + w2 * 8);
            gbase[(size_t)px * 128 + m * 32 + w2] = v;
        }
        __syncthreads();
    }
}

__global__ void k_grn(const float* __restrict__ gamma) {
    int b = blockIdx.x, t = threadIdx.x;
    float gx = sqrtf(g_sumsq[b * CEn + t]);
    __shared__ float sm[CEn];
    sm[t] = gx;
    __syncthreads();
    for (int o = 256; o > 0; o >>= 1) {
        if (t < o) sm[t] += sm[t + o];
        __syncthreads();
    }
    g_scale[b * CEn + t] = gamma[t] * (gx / (sm[0] * (1.f / (float)CEn) + EPSV)) + 1.f;
}

// ---------- shrink: fp16 mma GEMM (scale/beta folded) + residual ----------
#define S_SMEM 52224
__global__ void __launch_bounds__(256, 3)
k_shrink(const float* __restrict__ beta, const float* __restrict__ x, float* __restrict__ out) {
    extern __shared__ char sb[];
    uint32_t sbu = smem_u32(sb);
    int t = threadIdx.x, wid = t >> 5, lane = t & 31;
    int b = blockIdx.y, p0 = blockIdx.x * 64;
    const __half* gz = g_gelu + ((size_t)b * HW + p0) * CEn;
    float acc[8][4];
    #pragma unroll
    for (int n = 0; n < 8; n++) acc[n][0] = acc[n][1] = acc[n][2] = acc[n][3] = 0.f;
    uint32_t aA = sbu + 17408 + (wid * 16 + (lane & 15)) * 272 + (lane >> 4) * 16;
    uint32_t aB = sbu + ((lane & 7) + ((lane >> 4) & 1) * 8) * 272 + ((lane >> 3) & 1) * 16;
    for (int kt = 0; kt < 4; kt++) {
        __syncthreads();
        const uint4* s0 = (const uint4*)g_wsa;
        #pragma unroll
        for (int i = 0; i < 8; i++) {
            int idx = t + i * 256;
            int r = idx >> 4, q = idx & 15;
            uint4 v = s0[r * 64 + kt * 16 + q];
            *(uint4*)(sb + 17408 + r * 272 + q * 16) = v;
        }
        #pragma unroll
        for (int i = 0; i < 8; i++) {
            int idx = t + i * 256;
            int p = idx >> 5, q = idx & 31;
            int ce = kt * 128 + q * 4;
            uint2 raw = *(const uint2*)&gz[(size_t)p * CEn + ce];
            __half2 g01 = *(__half2*)&raw.x, g23 = *(__half2*)&raw.y;
            float4 a = *(const float4*)&g_scale[b * CEn + ce];
            float4 bt = *(const float4*)&beta[ce];
            float z0 = a.x * __low2float(g01) + bt.x;
            float z1 = a.y * __high2float(g01) + bt.y;
            float z2 = a.z * __low2float(g23) + bt.z;
            float z3 = a.w * __high2float(g23) + bt.w;
            *(uint2*)(sb + p * 272 + q * 8) = make_uint2(pkh2(z0, z1), pkh2(z2, z3));
        }
        __syncthreads();
        #pragma unroll
        for (int k = 0; k < 8; k++) {
            uint32_t ah[4];
            ldm4(ah, aA + k * 32);
            #pragma unroll
            for (int np = 0; np < 4; np++) {
                uint32_t bh[4];
                ldm4(bh, aB + np * 4352 + k * 32);
                mma_f16(acc[2 * np], ah, bh);
                mma_f16(acc[2 * np + 1], ah, bh + 2);
            }
        }
    }
    __syncthreads();
    float* s_out = (float*)sb;   // [128][68]
    int r0 = wid * 16 + (lane >> 2), cbase = (lane & 3) * 2;
    #pragma unroll
    for (int n = 0; n < 8; n++) {
        int cc = n * 8 + cbase;
        s_out[r0 * 68 + cc] = acc[n][0];
        s_out[r0 * 68 + cc + 1] = acc[n][1];
        s_out[(r0 + 8) * 68 + cc] = acc[n][2];
        s_out[(r0 + 8) * 68 + cc + 1] = acc[n][3];
    }
    __syncthreads();
    const float* xp = x + (size_t)b * Cn * HW + p0;
    float* op = out + (size_t)b * Cn * HW + p0;
    #pragma unroll
    for (int i = 0; i < 8; i++) {
        int idx = t + i * 256, oc = idx >> 4, p4 = (idx & 15) * 4;
        float4 v = *(float4*)&s_out[oc * 68 + p4];
        float4 xv = *(const float4*)&xp[(size_t)oc * HW + p4];
        v.x += xv.x; v.y += xv.y; v.z += xv.z; v.w += xv.w;
        *(float4*)&op[(size_t)oc * HW + p4] = v;
    }
}

// ---------- launch ----------
extern "C" void kernel_launch(void* const* d_in, const int* in_sizes, int n_in,
                              void* d_out, int out_size) {
    const float* x        = (const float*)d_in[0];
    const float* w_fc1    = (const float*)d_in[1];
    const float* ln1_w    = (const float*)d_in[2];
    const float* ln1_b    = (const float*)d_in[3];
    const float* w_fc2    = (const float*)d_in[4];
    const float* ln2_w    = (const float*)d_in[5];
    const float* ln2_b    = (const float*)d_in[6];
    const float* w_expand = (const float*)d_in[7];
    const float* w_shrink = (const float*)d_in[8];
    const float* grn_g    = (const float*)d_in[9];
    const float* grn_b    = (const float*)d_in[10];
    float* out = (float*)d_out;

    cudaFuncSetAttribute(k_expand, cudaFuncAttributeMaxDynamicSharedMemorySize, E_SMEM);
    cudaFuncSetAttribute(k_shrink, cudaFuncAttributeMaxDynamicSharedMemorySize, S_SMEM);

    k_wprep<<<256, 256>>>(w_expand, w_shrink);
    k_pool<<<Bn * Cn, 256>>>(x);
    k_fc<<<dim3(13, Bn), 256>>>(w_fc1, ln1_w, ln1_b, w_fc2);
    k_conv<<<Bn * Cn, 256>>>(x);
    k_expand<<<dim3(28, Bn), 256, E_SMEM>>>(ln2_w, ln2_b);
    k_grn<<<Bn, CEn>>>(grn_g);
    k_shrink<<<dim3(49, Bn), 256, S_SMEM>>>(grn_b, x, out);
}

// round 14
// speedup vs baseline: 1.3432x; 1.0013x over previous
#include <cuda_runtime.h>
#include <cuda_fp16.h>
#include <cstdint>
#include <math.h>

#define Bn 32
#define Cn 128
#define Hn 56
#define Wn 56
#define HW 3136
#define CEn 512
#define EPSV 1e-6f

__device__ float g_pooled[Bn * Cn];
__device__ float g_dyn[Bn * Cn * 25];
__device__ __half g_conv[(size_t)Bn * Cn * HW];    // fp16
__device__ __half g_gelu[(size_t)Bn * HW * CEn];   // [b][p][ce] fp16
__device__ float g_sumsq[Bn * CEn];
__device__ float g_scale[Bn * CEn];
__device__ uint32_t g_wea[32768];   // expand W fp16x2 [512][64]
__device__ uint32_t g_wsa[32768];   // shrink W fp16x2 [128][256]

// ---------- helpers ----------
__device__ __forceinline__ uint32_t smem_u32(const void* p) {
    uint32_t a;
    asm("{ .reg .u64 t; cvta.to.shared.u64 t, %1; cvt.u32.u64 %0, t; }" : "=r"(a) : "l"(p));
    return a;
}
__device__ __forceinline__ void ldm4(uint32_t* r, uint32_t a) {
    asm volatile("ldmatrix.sync.aligned.m8n8.x4.shared.b16 {%0,%1,%2,%3}, [%4];"
        : "=r"(r[0]), "=r"(r[1]), "=r"(r[2]), "=r"(r[3]) : "r"(a));
}
__device__ __forceinline__ void mma_f16(float* c, const uint32_t* a, const uint32_t* b) {
    asm volatile("mma.sync.aligned.m16n8k16.row.col.f32.f16.f16.f32 "
        "{%0,%1,%2,%3},{%4,%5,%6,%7},{%8,%9},{%0,%1,%2,%3};"
        : "+f"(c[0]), "+f"(c[1]), "+f"(c[2]), "+f"(c[3])
        : "r"(a[0]), "r"(a[1]), "r"(a[2]), "r"(a[3]), "r"(b[0]), "r"(b[1]));
}
__device__ __forceinline__ uint32_t pkh2(float a, float b) {
    __half2 h = __floats2half2_rn(a, b);
    return *(uint32_t*)&h;
}
// Abramowitz-Stegun 7.1.26 erf approximation (abs err <= 1.5e-7)
__device__ __forceinline__ float gelu_f(float v) {
    float z = fabsf(v) * 0.7071067811865476f;
    float t = __fdividef(1.f, fmaf(0.3275911f, z, 1.f));
    float p = t * fmaf(t, fmaf(t, fmaf(t, fmaf(t, 1.061405429f, -1.453152027f),
                1.421413741f), -0.284496736f), 0.254829592f);
    float erfv = 1.f - p * __expf(-z * z);
    erfv = copysignf(erfv, v);
    return 0.5f * v * (1.f + erfv);
}

// ---------- weight preconversion (+ sumsq zero), single launch ----------
__global__ void k_wprep(const float* __restrict__ we, const float* __restrict__ ws) {
    int g = blockIdx.x * 256 + threadIdx.x;         // 65536
    if (g < Bn * CEn) g_sumsq[g] = 0.f;
    int which = g >> 15, r = g & 32767;
    int shift = which ? 8 : 6;
    const float* src = which ? ws : we;
    int kp = r & ((1 << shift) - 1), row = r >> shift;
    const float* s = src + (size_t)row * (2 << shift) + 2 * kp;
    (which ? g_wsa : g_wea)[(row << shift) + kp] = pkh2(s[0], s[1]);
}

// ---------- small kernels ----------
__global__ void k_pool(const float* __restrict__ x) {
    int bc = blockIdx.x;
    const float* p = x + (size_t)bc * HW;
    int t = threadIdx.x, lane = t & 31, wid = t >> 5;
    float s = 0.f;
    for (int i = t; i < HW / 4; i += 256) {
        float4 v = reinterpret_cast<const float4*>(p)[i];
        s += v.x + v.y + v.z + v.w;
    }
    #pragma unroll
    for (int o = 16; o > 0; o >>= 1) s += __shfl_xor_sync(~0u, s, o);
    __shared__ float sm[8];
    if (lane == 0) sm[wid] = s;
    __syncthreads();
    if (t == 0) {
        float a = 0.f;
        #pragma unroll
        for (int i = 0; i < 8; i++) a += sm[i];
        g_pooled[bc] = a * (1.f / (float)HW);
    }
}

// fc1+LN1 (warp 0, redundant per block) then fc2
__global__ void k_fc(const float* __restrict__ w_fc1, const float* __restrict__ ln1w,
                     const float* __restrict__ ln1b, const float* __restrict__ w_fc2) {
    int b = blockIdx.y, t = threadIdx.x;
    __shared__ float sh[32];
    if (t < 32) {
        const float* sp = g_pooled + b * Cn;
        const float* wr = w_fc1 + t * Cn;
        float a = 0.f;
        #pragma unroll
        for (int i = 0; i < Cn; i++) a += wr[i] * sp[i];
        float u = a;
        #pragma unroll
        for (int o = 16; o > 0; o >>= 1) u += __shfl_xor_sync(~0u, u, o);
        u *= (1.f / 32.f);
        float d = a - u, v = d * d;
        #pragma unroll
        for (int o = 16; o > 0; o >>= 1) v += __shfl_xor_sync(~0u, v, o);
        v *= (1.f / 32.f);
        sh[t] = d * rsqrtf(v + EPSV) * ln1w[t] + ln1b[t];
    }
    __syncthreads();
    int i = blockIdx.x * 256 + t;
    if (i < Cn * 25) {
        const float* wr = w_fc2 + i * 32;
        float a = 0.f;
        #pragma unroll
        for (int j = 0; j < 32; j++) a += wr[j] * sh[j];
        g_dyn[b * Cn * 25 + i] = a;
    }
}

// ---------- conv: kernel coeffs in smem, high occupancy ----------
__global__ void __launch_bounds__(256, 8) k_conv(const float* __restrict__ x) {
    int bc = blockIdx.x;
    __shared__ float tile[60 * 60];
    __shared__ float skk[32];
    int t = threadIdx.x;
    if (t < 25) skk[t] = g_dyn[bc * 25 + t];
    const float* xp = x + (size_t)bc * HW;
    for (int i = t; i < 3600; i += 256) {
        int r = i / 60, cc = i % 60, h = r - 2, w = cc - 2;
        tile[i] = (h >= 0 && h < Hn && w >= 0 && w < Wn) ? xp[h * Wn + w] : 0.f;
    }
    __syncthreads();
    __half* op = g_conv + (size_t)bc * HW;
    for (int q = t; q < 784; q += 256) {
        int h = q / 14, w0 = (q % 14) * 4;
        float a0 = 0.f, a1 = 0.f, a2 = 0.f, a3 = 0.f;
        #pragma unroll
        for (int i = 0; i < 5; i++) {
            const float* r = &tile[(h + i) * 60 + w0];
            float r0 = r[0], r1 = r[1], r2 = r[2], r3 = r[3];
            float r4 = r[4], r5 = r[5], r6 = r[6], r7 = r[7];
            const float* kr = &skk[i * 5];
            float k0 = kr[0], k1 = kr[1], k2 = kr[2], k3 = kr[3], k4 = kr[4];
            a0 += k0 * r0 + k1 * r1 + k2 * r2 + k3 * r3 + k4 * r4;
            a1 += k0 * r1 + k1 * r2 + k2 * r3 + k3 * r4 + k4 * r5;
            a2 += k0 * r2 + k1 * r3 + k2 * r4 + k3 * r5 + k4 * r6;
            a3 += k0 * r3 + k1 * r4 + k2 * r5 + k3 * r6 + k4 * r7;
        }
        *reinterpret_cast<uint2*>(&op[q * 4]) = make_uint2(pkh2(a0, a1), pkh2(a2, a3));
    }
}

// ---------- expand: LN2 + fp16 mma GEMM + gelu + GRN sumsq ----------
#define E_RB 30720
#define E_SMEM 69760
__global__ void __launch_bounds__(256, 2)
k_expand(const float* __restrict__ ln2w, const float* __restrict__ ln2b) {
    extern __shared__ char sb[];
    uint32_t sbu = smem_u32(sb);
    int t = threadIdx.x, wid = t >> 5, lane = t & 31;
    int b = blockIdx.y, p0 = blockIdx.x * 112;
    float* s_lnw = (float*)(sb + 65536);
    float* s_lnb = (float*)(sb + 66048);
    float* r1 = (float*)(sb + 66560);
    float* r2 = (float*)(sb + 67456);
    float* smu = (float*)(sb + 68352);
    float* srs = (float*)(sb + 68800);
    float* s_sq = (float*)(sb + 69248);
    if (t < 128) { s_lnw[t] = ln2w[t]; s_lnb[t] = ln2b[t]; }
    const __half* cp = g_conv + (size_t)b * Cn * HW + p0;
    #pragma unroll
    for (int i = 0; i < 7; i++) {
        int idx = t + i * 256;
        int c = idx / 14, qq = idx % 14;
        uint4 v = *(const uint4*)&cp[(size_t)c * HW + qq * 8];
        uint32_t* d = (uint32_t*)(sb + E_RB + c * 260 + qq * 16);
        d[0] = v.x; d[1] = v.y; d[2] = v.z; d[3] = v.w;
    }
    __syncthreads();
    if (t < 224) {
        int p = t % 112, h = t / 112;
        float s = 0.f, s2 = 0.f;
        for (int c = h * 64; c < h * 64 + 64; c++) {
            float v = __half2float(*(__half*)(sb + E_RB + c * 260 + 2 * p));
            s += v; s2 += v * v;
        }
        r1[t] = s; r2[t] = s2;
    }
    __syncthreads();
    if (t < 112) {
        float s = r1[t] + r1[112 + t], s2 = r2[t] + r2[112 + t];
        float mu = s * (1.f / 128.f);
        smu[t] = mu;
        srs[t] = rsqrtf(s2 * (1.f / 128.f) - mu * mu + EPSV);
    }
    __syncthreads();
    #pragma unroll
    for (int i = 0; i < 28; i++) {
        int idx = t + i * 256, p = idx >> 6, cp2 = idx & 63, c0 = cp2 * 2;
        float mu = smu[p], rs = srs[p];
        float x0 = __half2float(*(__half*)(sb + E_RB + c0 * 260 + 2 * p));
        float x1 = __half2float(*(__half*)(sb + E_RB + (c0 + 1) * 260 + 2 * p));
        float v0 = (x0 - mu) * rs * s_lnw[c0] + s_lnb[c0];
        float v1 = (x1 - mu) * rs * s_lnw[c0 + 1] + s_lnb[c0 + 1];
        *(uint32_t*)(sb + p * 272 + cp2 * 4) = pkh2(v0, v1);
    }
    __syncthreads();
    uint32_t aA = sbu + E_RB + (wid * 16 + (lane & 15)) * 272 + (lane >> 4) * 16;
    uint32_t aB = sbu + ((lane & 7) + ((lane >> 4) & 1) * 8) * 272 + ((lane >> 3) & 1) * 16;
    int r0 = wid * 16 + (lane >> 2), cbase = (lane & 3) * 2;
    uint2* gbase = (uint2*)g_gelu + ((size_t)b * HW + p0) * 128;
    for (int m = 0; m < 4; m++) {
        if (t < 128) s_sq[t] = 0.f;
        const uint4* s0 = (const uint4*)g_wea;
        #pragma unroll
        for (int i = 0; i < 8; i++) {
            int idx = t + i * 256;
            int r = idx >> 4, q = idx & 15;
            uint4 v = s0[(m * 128 + r) * 16 + q];
            *(uint4*)(sb + E_RB + r * 272 + q * 16) = v;
        }
        __syncthreads();
        float acc[14][4];
        #pragma unroll
        for (int n = 0; n < 14; n++) { acc[n][0] = acc[n][1] = acc[n][2] = acc[n][3] = 0.f; }
        #pragma unroll
        for (int k = 0; k < 8; k++) {
            uint32_t ah[4];
            ldm4(ah, aA + k * 32);
            #pragma unroll
            for (int np = 0; np < 7; np++) {
                uint32_t bh[4];
                ldm4(bh, aB + np * 4352 + k * 32);
                mma_f16(acc[2 * np], ah, bh);
                mma_f16(acc[2 * np + 1], ah, bh + 2);
            }
        }
        __syncthreads();      // A dead; region B becomes gout [px][oc] stride 264B
        float ss0 = 0.f, ss1 = 0.f;
        #pragma unroll
        for (int n = 0; n < 14; n++) {
            int cc = n * 8 + cbase;           // pixel index
            float g0 = gelu_f(acc[n][0]), g1 = gelu_f(acc[n][1]);
            float g2 = gelu_f(acc[n][2]), g3 = gelu_f(acc[n][3]);
            ss0 += g0 * g0 + g1 * g1;
            ss1 += g2 * g2 + g3 * g3;
            *(__half*)(sb + E_RB + cc * 264 + 2 * r0) = __float2half_rn(g0);
            *(__half*)(sb + E_RB + (cc + 1) * 264 + 2 * r0) = __float2half_rn(g1);
            *(__half*)(sb + E_RB + cc * 264 + 2 * (r0 + 8)) = __float2half_rn(g2);
            *(__half*)(sb + E_RB + (cc + 1) * 264 + 2 * (r0 + 8)) = __float2half_rn(g3);
        }
        atomicAdd(&s_sq[r0], ss0);
        atomicAdd(&s_sq[r0 + 8], ss1);
        __syncthreads();
        if (t < 128) atomicAdd(&g_sumsq[b * CEn + m * 128 + t], s_sq[t]);
        // store pass: uint2 (8B) wide, coalesced
        #pragma unroll
        for (int i = 0; i < 14; i++) {
            int idx = t + i * 256;                 // 3584 uint2
            int px = idx >> 5, w2 = idx & 31;
            uint2 v = *(uint2*)(sb + E_RB + px * 264 + w2 * 8);
            gbase[(size_t)px * 128 + m * 32 + w2] = v;
        }
        __syncthreads();
    }
}

__global__ void k_grn(const float* __restrict__ gamma) {
    int b = blockIdx.x, t = threadIdx.x;
    float gx = sqrtf(g_sumsq[b * CEn + t]);
    __shared__ float sm[CEn];
    sm[t] = gx;
    __syncthreads();
    for (int o = 256; o > 0; o >>= 1) {
        if (t < o) sm[t] += sm[t + o];
        __syncthreads();
    }
    g_scale[b * CEn + t] = gamma[t] * (gx / (sm[0] * (1.f / (float)CEn) + EPSV)) + 1.f;
}

// ---------- shrink: fp16 mma GEMM (scale/beta folded) + residual ----------
#define S_SMEM 52224
__global__ void __launch_bounds__(256, 3)
k_shrink(const float* __restrict__ beta, const float* __restrict__ x, float* __restrict__ out) {
    extern __shared__ char sb[];
    uint32_t sbu = smem_u32(sb);
    int t = threadIdx.x, wid = t >> 5, lane = t & 31;
    int b = blockIdx.y, p0 = blockIdx.x * 64;
    const __half* gz = g_gelu + ((size_t)b * HW + p0) * CEn;
    float acc[8][4];
    #pragma unroll
    for (int n = 0; n < 8; n++) acc[n][0] = acc[n][1] = acc[n][2] = acc[n][3] = 0.f;
    uint32_t aA = sbu + 17408 + (wid * 16 + (lane & 15)) * 272 + (lane >> 4) * 16;
    uint32_t aB = sbu + ((lane & 7) + ((lane >> 4) & 1) * 8) * 272 + ((lane >> 3) & 1) * 16;
    for (int kt = 0; kt < 4; kt++) {
        __syncthreads();
        const uint4* s0 = (const uint4*)g_wsa;
        #pragma unroll
        for (int i = 0; i < 8; i++) {
            int idx = t + i * 256;
            int r = idx >> 4, q = idx & 15;
            uint4 v = s0[r * 64 + kt * 16 + q];
            *(uint4*)(sb + 17408 + r * 272 + q * 16) = v;
        }
        #pragma unroll
        for (int i = 0; i < 8; i++) {
            int idx = t + i * 256;
            int p = idx >> 5, q = idx & 31;
            int ce = kt * 128 + q * 4;
            uint2 raw = *(const uint2*)&gz[(size_t)p * CEn + ce];
            __half2 g01 = *(__half2*)&raw.x, g23 = *(__half2*)&raw.y;
            float4 a = *(const float4*)&g_scale[b * CEn + ce];
            float4 bt = *(const float4*)&beta[ce];
            float z0 = a.x * __low2float(g01) + bt.x;
            float z1 = a.y * __high2float(g01) + bt.y;
            float z2 = a.z * __low2float(g23) + bt.z;
            float z3 = a.w * __high2float(g23) + bt.w;
            *(uint2*)(sb + p * 272 + q * 8) = make_uint2(pkh2(z0, z1), pkh2(z2, z3));
        }
        __syncthreads();
        #pragma unroll
        for (int k = 0; k < 8; k++) {
            uint32_t ah[4];
            ldm4(ah, aA + k * 32);
            #pragma unroll
            for (int np = 0; np < 4; np++) {
                uint32_t bh[4];
                ldm4(bh, aB + np * 4352 + k * 32);
                mma_f16(acc[2 * np], ah, bh);
                mma_f16(acc[2 * np + 1], ah, bh + 2);
            }
        }
    }
    __syncthreads();
    float* s_out = (float*)sb;   // [128][68]
    int r0 = wid * 16 + (lane >> 2), cbase = (lane & 3) * 2;
    #pragma unroll
    for (int n = 0; n < 8; n++) {
        int cc = n * 8 + cbase;
        s_out[r0 * 68 + cc] = acc[n][0];
        s_out[r0 * 68 + cc + 1] = acc[n][1];
        s_out[(r0 + 8) * 68 + cc] = acc[n][2];
        s_out[(r0 + 8) * 68 + cc + 1] = acc[n][3];
    }
    __syncthreads();
    const float* xp = x + (size_t)b * Cn * HW + p0;
    float* op = out + (size_t)b * Cn * HW + p0;
    #pragma unroll
    for (int i = 0; i < 8; i++) {
        int idx = t + i * 256, oc = idx >> 4, p4 = (idx & 15) * 4;
        float4 v = *(float4*)&s_out[oc * 68 + p4];
        float4 xv = *(const float4*)&xp[(size_t)oc * HW + p4];
        v.x += xv.x; v.y += xv.y; v.z += xv.z; v.w += xv.w;
        *(float4*)&op[(size_t)oc * HW + p4] = v;
    }
}

// ---------- launch ----------
extern "C" void kernel_launch(void* const* d_in, const int* in_sizes, int n_in,
                              void* d_out, int out_size) {
    const float* x        = (const float*)d_in[0];
    const float* w_fc1    = (const float*)d_in[1];
    const float* ln1_w    = (const float*)d_in[2];
    const float* ln1_b    = (const float*)d_in[3];
    const float* w_fc2    = (const float*)d_in[4];
    const float* ln2_w    = (const float*)d_in[5];
    const float* ln2_b    = (const float*)d_in[6];
    const float* w_expand = (const float*)d_in[7];
    const float* w_shrink = (const float*)d_in[8];
    const float* grn_g    = (const float*)d_in[9];
    const float* grn_b    = (const float*)d_in[10];
    float* out = (float*)d_out;

    cudaFuncSetAttribute(k_expand, cudaFuncAttributeMaxDynamicSharedMemorySize, E_SMEM);
    cudaFuncSetAttribute(k_shrink, cudaFuncAttributeMaxDynamicSharedMemorySize, S_SMEM);

    k_wprep<<<256, 256>>>(w_expand, w_shrink);
    k_pool<<<Bn * Cn, 256>>>(x);
    k_fc<<<dim3(13, Bn), 256>>>(w_fc1, ln1_w, ln1_b, w_fc2);
    k_conv<<<Bn * Cn, 256>>>(x);
    k_expand<<<dim3(28, Bn), 256, E_SMEM>>>(ln2_w, ln2_b);
    k_grn<<<Bn, CEn>>>(grn_g);
    k_shrink<<<dim3(49, Bn), 256, S_SMEM>>>(grn_b, x, out);
}

// round 15
// speedup vs baseline: 1.7006x; 1.2661x over previous
#include <cuda_runtime.h>
#include <cuda_fp16.h>
#include <cstdint>
#include <math.h>

#define Bn 32
#define Cn 128
#define Hn 56
#define Wn 56
#define HW 3136
#define CEn 512
#define EPSV 1e-6f

__device__ float g_pooled[Bn * Cn];
__device__ float g_dyn[Bn * Cn * 25];
__device__ __half g_conv[(size_t)Bn * Cn * HW];    // fp16
__device__ __half g_gelu[(size_t)Bn * HW * CEn];   // [b][p][ce] fp16
__device__ float g_sumsq[Bn * CEn];
__device__ float g_scale[Bn * CEn];
__device__ uint32_t g_wea[32768];   // expand W fp16x2 [512][64]
__device__ uint32_t g_wsa[32768];   // shrink W fp16x2 [128][256]

// ---------- helpers ----------
__device__ __forceinline__ uint32_t smem_u32(const void* p) {
    uint32_t a;
    asm("{ .reg .u64 t; cvta.to.shared.u64 t, %1; cvt.u32.u64 %0, t; }" : "=r"(a) : "l"(p));
    return a;
}
__device__ __forceinline__ void ldm4(uint32_t* r, uint32_t a) {
    asm volatile("ldmatrix.sync.aligned.m8n8.x4.shared.b16 {%0,%1,%2,%3}, [%4];"
        : "=r"(r[0]), "=r"(r[1]), "=r"(r[2]), "=r"(r[3]) : "r"(a));
}
__device__ __forceinline__ void mma_f16(float* c, const uint32_t* a, const uint32_t* b) {
    asm volatile("mma.sync.aligned.m16n8k16.row.col.f32.f16.f16.f32 "
        "{%0,%1,%2,%3},{%4,%5,%6,%7},{%8,%9},{%0,%1,%2,%3};"
        : "+f"(c[0]), "+f"(c[1]), "+f"(c[2]), "+f"(c[3])
        : "r"(a[0]), "r"(a[1]), "r"(a[2]), "r"(a[3]), "r"(b[0]), "r"(b[1]));
}
__device__ __forceinline__ uint32_t pkh2(float a, float b) {
    __half2 h = __floats2half2_rn(a, b);
    return *(uint32_t*)&h;
}
// Abramowitz-Stegun 7.1.26 erf approximation (abs err <= 1.5e-7)
__device__ __forceinline__ float gelu_f(float v) {
    float z = fabsf(v) * 0.7071067811865476f;
    float t = __fdividef(1.f, fmaf(0.3275911f, z, 1.f));
    float p = t * fmaf(t, fmaf(t, fmaf(t, fmaf(t, 1.061405429f, -1.453152027f),
                1.421413741f), -0.284496736f), 0.254829592f);
    float erfv = 1.f - p * __expf(-z * z);
    erfv = copysignf(erfv, v);
    return 0.5f * v * (1.f + erfv);
}

// ---------- weight preconversion (+ sumsq zero), single launch ----------
__global__ void k_wprep(const float* __restrict__ we, const float* __restrict__ ws) {
    int g = blockIdx.x * 256 + threadIdx.x;         // 65536
    if (g < Bn * CEn) g_sumsq[g] = 0.f;
    int which = g >> 15, r = g & 32767;
    int shift = which ? 8 : 6;
    const float* src = which ? ws : we;
    int kp = r & ((1 << shift) - 1), row = r >> shift;
    const float* s = src + (size_t)row * (2 << shift) + 2 * kp;
    (which ? g_wsa : g_wea)[(row << shift) + kp] = pkh2(s[0], s[1]);
}

// ---------- small kernels ----------
__global__ void k_pool(const float* __restrict__ x) {
    int bc = blockIdx.x;
    const float* p = x + (size_t)bc * HW;
    int t = threadIdx.x, lane = t & 31, wid = t >> 5;
    float s = 0.f;
    for (int i = t; i < HW / 4; i += 256) {
        float4 v = reinterpret_cast<const float4*>(p)[i];
        s += v.x + v.y + v.z + v.w;
    }
    #pragma unroll
    for (int o = 16; o > 0; o >>= 1) s += __shfl_xor_sync(~0u, s, o);
    __shared__ float sm[8];
    if (lane == 0) sm[wid] = s;
    __syncthreads();
    if (t == 0) {
        float a = 0.f;
        #pragma unroll
        for (int i = 0; i < 8; i++) a += sm[i];
        g_pooled[bc] = a * (1.f / (float)HW);
    }
}

// fc1+LN1 (warp 0, redundant per block) then fc2
__global__ void k_fc(const float* __restrict__ w_fc1, const float* __restrict__ ln1w,
                     const float* __restrict__ ln1b, const float* __restrict__ w_fc2) {
    int b = blockIdx.y, t = threadIdx.x;
    __shared__ float sh[32];
    if (t < 32) {
        const float* sp = g_pooled + b * Cn;
        const float* wr = w_fc1 + t * Cn;
        float a = 0.f;
        #pragma unroll
        for (int i = 0; i < Cn; i++) a += wr[i] * sp[i];
        float u = a;
        #pragma unroll
        for (int o = 16; o > 0; o >>= 1) u += __shfl_xor_sync(~0u, u, o);
        u *= (1.f / 32.f);
        float d = a - u, v = d * d;
        #pragma unroll
        for (int o = 16; o > 0; o >>= 1) v += __shfl_xor_sync(~0u, v, o);
        v *= (1.f / 32.f);
        sh[t] = d * rsqrtf(v + EPSV) * ln1w[t] + ln1b[t];
    }
    __syncthreads();
    int i = blockIdx.x * 256 + t;
    if (i < Cn * 25) {
        const float* wr = w_fc2 + i * 32;
        float a = 0.f;
        #pragma unroll
        for (int j = 0; j < 32; j++) a += wr[j] * sh[j];
        g_dyn[b * Cn * 25 + i] = a;
    }
}

// ---------- conv: 4x4 output patch per thread (vertical reuse), vector fill ----------
__global__ void __launch_bounds__(256) k_conv(const float* __restrict__ x) {
    int bc = blockIdx.x;
    __shared__ float tile[60 * 60];
    int t = threadIdx.x;
    // vectorized zero (900 float4)
    for (int i = t; i < 900; i += 256) ((float4*)tile)[i] = make_float4(0.f, 0.f, 0.f, 0.f);
    float kk[25];
    const float* dp = g_dyn + bc * 25;
    #pragma unroll
    for (int i = 0; i < 25; i++) kk[i] = dp[i];
    __syncthreads();
    // interior fill: 784 float4 LDG, 2 float2 STS each (col offset +2)
    const float* xp = x + (size_t)bc * HW;
    for (int i = t; i < 784; i += 256) {
        int r = i / 14, c4 = (i % 14) * 4;
        float4 v = *(const float4*)&xp[r * 56 + c4];
        float* d = &tile[(r + 2) * 60 + c4 + 2];
        *(float2*)d = make_float2(v.x, v.y);
        *(float2*)(d + 2) = make_float2(v.z, v.w);
    }
    __syncthreads();
    __half* op = g_conv + (size_t)bc * HW;
    if (t < 196) {
        int hb = t / 14, w0 = (t % 14) * 4;   // output rows 4hb..4hb+3, cols w0..w0+3
        float acc[4][4];
        #pragma unroll
        for (int a = 0; a < 4; a++)
            #pragma unroll
            for (int c = 0; c < 4; c++) acc[a][c] = 0.f;
        #pragma unroll
        for (int ir = 0; ir < 8; ir++) {
            const float* rp = &tile[(hb * 4 + ir) * 60 + w0];
            float4 u0 = *(const float4*)rp;
            float4 u1 = *(const float4*)(rp + 4);
            float v[8] = {u0.x, u0.y, u0.z, u0.w, u1.x, u1.y, u1.z, u1.w};
            #pragma unroll
            for (int ki = 0; ki < 5; ki++) {
                int orow = ir - ki;
                if (orow >= 0 && orow < 4) {
                    #pragma unroll
                    for (int kj = 0; kj < 5; kj++) {
                        float kv = kk[ki * 5 + kj];
                        acc[orow][0] = fmaf(kv, v[kj],     acc[orow][0]);
                        acc[orow][1] = fmaf(kv, v[kj + 1], acc[orow][1]);
                        acc[orow][2] = fmaf(kv, v[kj + 2], acc[orow][2]);
                        acc[orow][3] = fmaf(kv, v[kj + 3], acc[orow][3]);
                    }
                }
            }
        }
        #pragma unroll
        for (int orr = 0; orr < 4; orr++) {
            *(uint2*)&op[(hb * 4 + orr) * 56 + w0] =
                make_uint2(pkh2(acc[orr][0], acc[orr][1]), pkh2(acc[orr][2], acc[orr][3]));
        }
    }
}

// ---------- expand: LN2 + fp16 mma GEMM + gelu + GRN sumsq ----------
#define E_RB 30720
#define E_SMEM 69760
__global__ void __launch_bounds__(256, 2)
k_expand(const float* __restrict__ ln2w, const float* __restrict__ ln2b) {
    extern __shared__ char sb[];
    uint32_t sbu = smem_u32(sb);
    int t = threadIdx.x, wid = t >> 5, lane = t & 31;
    int b = blockIdx.y, p0 = blockIdx.x * 112;
    float* s_lnw = (float*)(sb + 65536);
    float* s_lnb = (float*)(sb + 66048);
    float* r1 = (float*)(sb + 66560);
    float* r2 = (float*)(sb + 67456);
    float* smu = (float*)(sb + 68352);
    float* srs = (float*)(sb + 68800);
    float* s_sq = (float*)(sb + 69248);
    if (t < 128) { s_lnw[t] = ln2w[t]; s_lnb[t] = ln2b[t]; }
    const __half* cp = g_conv + (size_t)b * Cn * HW + p0;
    #pragma unroll
    for (int i = 0; i < 7; i++) {
        int idx = t + i * 256;
        int c = idx / 14, qq = idx % 14;
        uint4 v = *(const uint4*)&cp[(size_t)c * HW + qq * 8];
        uint32_t* d = (uint32_t*)(sb + E_RB + c * 260 + qq * 16);
        d[0] = v.x; d[1] = v.y; d[2] = v.z; d[3] = v.w;
    }
    __syncthreads();
    if (t < 224) {
        int p = t % 112, h = t / 112;
        float s = 0.f, s2 = 0.f;
        for (int c = h * 64; c < h * 64 + 64; c++) {
            float v = __half2float(*(__half*)(sb + E_RB + c * 260 + 2 * p));
            s += v; s2 += v * v;
        }
        r1[t] = s; r2[t] = s2;
    }
    __syncthreads();
    if (t < 112) {
        float s = r1[t] + r1[112 + t], s2 = r2[t] + r2[112 + t];
        float mu = s * (1.f / 128.f);
        smu[t] = mu;
        srs[t] = rsqrtf(s2 * (1.f / 128.f) - mu * mu + EPSV);
    }
    __syncthreads();
    #pragma unroll
    for (int i = 0; i < 28; i++) {
        int idx = t + i * 256, p = idx >> 6, cp2 = idx & 63, c0 = cp2 * 2;
        float mu = smu[p], rs = srs[p];
        float x0 = __half2float(*(__half*)(sb + E_RB + c0 * 260 + 2 * p));
        float x1 = __half2float(*(__half*)(sb + E_RB + (c0 + 1) * 260 + 2 * p));
        float v0 = (x0 - mu) * rs * s_lnw[c0] + s_lnb[c0];
        float v1 = (x1 - mu) * rs * s_lnw[c0 + 1] + s_lnb[c0 + 1];
        *(uint32_t*)(sb + p * 272 + cp2 * 4) = pkh2(v0, v1);
    }
    __syncthreads();
    uint32_t aA = sbu + E_RB + (wid * 16 + (lane & 15)) * 272 + (lane >> 4) * 16;
    uint32_t aB = sbu + ((lane & 7) + ((lane >> 4) & 1) * 8) * 272 + ((lane >> 3) & 1) * 16;
    int r0 = wid * 16 + (lane >> 2), cbase = (lane & 3) * 2;
    uint2* gbase = (uint2*)g_gelu + ((size_t)b * HW + p0) * 128;
    for (int m = 0; m < 4; m++) {
        if (t < 128) s_sq[t] = 0.f;
        const uint4* s0 = (const uint4*)g_wea;
        #pragma unroll
        for (int i = 0; i < 8; i++) {
            int idx = t + i * 256;
            int r = idx >> 4, q = idx & 15;
            uint4 v = s0[(m * 128 + r) * 16 + q];
            *(uint4*)(sb + E_RB + r * 272 + q * 16) = v;
        }
        __syncthreads();
        float acc[14][4];
        #pragma unroll
        for (int n = 0; n < 14; n++) { acc[n][0] = acc[n][1] = acc[n][2] = acc[n][3] = 0.f; }
        #pragma unroll
        for (int k = 0; k < 8; k++) {
            uint32_t ah[4];
            ldm4(ah, aA + k * 32);
            #pragma unroll
            for (int np = 0; np < 7; np++) {
                uint32_t bh[4];
                ldm4(bh, aB + np * 4352 + k * 32);
                mma_f16(acc[2 * np], ah, bh);
                mma_f16(acc[2 * np + 1], ah, bh + 2);
            }
        }
        __syncthreads();      // A dead; region B becomes gout [px][oc] stride 264B
        float ss0 = 0.f, ss1 = 0.f;
        #pragma unroll
        for (int n = 0; n < 14; n++) {
            int cc = n * 8 + cbase;           // pixel index
            float g0 = gelu_f(acc[n][0]), g1 = gelu_f(acc[n][1]);
            float g2 = gelu_f(acc[n][2]), g3 = gelu_f(acc[n][3]);
            ss0 += g0 * g0 + g1 * g1;
            ss1 += g2 * g2 + g3 * g3;
            *(__half*)(sb + E_RB + cc * 264 + 2 * r0) = __float2half_rn(g0);
            *(__half*)(sb + E_RB + (cc + 1) * 264 + 2 * r0) = __float2half_rn(g1);
            *(__half*)(sb + E_RB + cc * 264 + 2 * (r0 + 8)) = __float2half_rn(g2);
            *(__half*)(sb + E_RB + (cc + 1) * 264 + 2 * (r0 + 8)) = __float2half_rn(g3);
        }
        atomicAdd(&s_sq[r0], ss0);
        atomicAdd(&s_sq[r0 + 8], ss1);
        __syncthreads();
        if (t < 128) atomicAdd(&g_sumsq[b * CEn + m * 128 + t], s_sq[t]);
        // store pass: uint2 (8B) wide, coalesced
        #pragma unroll
        for (int i = 0; i < 14; i++) {
            int idx = t + i * 256;                 // 3584 uint2
            int px = idx >> 5, w2 = idx & 31;
            uint2 v = *(uint2*)(sb + E_RB + px * 264 + w2 * 8);
            gbase[(size_t)px * 128 + m * 32 + w2] = v;
        }
        __syncthreads();
    }
}

__global__ void k_grn(const float* __restrict__ gamma) {
    int b = blockIdx.x, t = threadIdx.x;
    float gx = sqrtf(g_sumsq[b * CEn + t]);
    __shared__ float sm[CEn];
    sm[t] = gx;
    __syncthreads();
    for (int o = 256; o > 0; o >>= 1) {
        if (t < o) sm[t] += sm[t + o];
        __syncthreads();
    }
    g_scale[b * CEn + t] = gamma[t] * (gx / (sm[0] * (1.f / (float)CEn) + EPSV)) + 1.f;
}

// ---------- shrink: fp16 mma GEMM (scale/beta folded) + residual ----------
#define S_SMEM 52224
__global__ void __launch_bounds__(256, 3)
k_shrink(const float* __restrict__ beta, const float* __restrict__ x, float* __restrict__ out) {
    extern __shared__ char sb[];
    uint32_t sbu = smem_u32(sb);
    int t = threadIdx.x, wid = t >> 5, lane = t & 31;
    int b = blockIdx.y, p0 = blockIdx.x * 64;
    const __half* gz = g_gelu + ((size_t)b * HW + p0) * CEn;
    float acc[8][4];
    #pragma unroll
    for (int n = 0; n < 8; n++) acc[n][0] = acc[n][1] = acc[n][2] = acc[n][3] = 0.f;
    uint32_t aA = sbu + 17408 + (wid * 16 + (lane & 15)) * 272 + (lane >> 4) * 16;
    uint32_t aB = sbu + ((lane & 7) + ((lane >> 4) & 1) * 8) * 272 + ((lane >> 3) & 1) * 16;
    for (int kt = 0; kt < 4; kt++) {
        __syncthreads();
        const uint4* s0 = (const uint4*)g_wsa;
        #pragma unroll
        for (int i = 0; i < 8; i++) {
            int idx = t + i * 256;
            int r = idx >> 4, q = idx & 15;
            uint4 v = s0[r * 64 + kt * 16 + q];
            *(uint4*)(sb + 17408 + r * 272 + q * 16) = v;
        }
        #pragma unroll
        for (int i = 0; i < 8; i++) {
            int idx = t + i * 256;
            int p = idx >> 5, q = idx & 31;
            int ce = kt * 128 + q * 4;
            uint2 raw = *(const uint2*)&gz[(size_t)p * CEn + ce];
            __half2 g01 = *(__half2*)&raw.x, g23 = *(__half2*)&raw.y;
            float4 a = *(const float4*)&g_scale[b * CEn + ce];
            float4 bt = *(const float4*)&beta[ce];
            float z0 = a.x * __low2float(g01) + bt.x;
            float z1 = a.y * __high2float(g01) + bt.y;
            float z2 = a.z * __low2float(g23) + bt.z;
            float z3 = a.w * __high2float(g23) + bt.w;
            *(uint2*)(sb + p * 272 + q * 8) = make_uint2(pkh2(z0, z1), pkh2(z2, z3));
        }
        __syncthreads();
        #pragma unroll
        for (int k = 0; k < 8; k++) {
            uint32_t ah[4];
            ldm4(ah, aA + k * 32);
            #pragma unroll
            for (int np = 0; np < 4; np++) {
                uint32_t bh[4];
                ldm4(bh, aB + np * 4352 + k * 32);
                mma_f16(acc[2 * np], ah, bh);
                mma_f16(acc[2 * np + 1], ah, bh + 2);
            }
        }
    }
    __syncthreads();
    float* s_out = (float*)sb;   // [128][68]
    int r0 = wid * 16 + (lane >> 2), cbase = (lane & 3) * 2;
    #pragma unroll
    for (int n = 0; n < 8; n++) {
        int cc = n * 8 + cbase;
        s_out[r0 * 68 + cc] = acc[n][0];
        s_out[r0 * 68 + cc + 1] = acc[n][1];
        s_out[(r0 + 8) * 68 + cc] = acc[n][2];
        s_out[(r0 + 8) * 68 + cc + 1] = acc[n][3];
    }
    __syncthreads();
    const float* xp = x + (size_t)b * Cn * HW + p0;
    float* op = out + (size_t)b * Cn * HW + p0;
    #pragma unroll
    for (int i = 0; i < 8; i++) {
        int idx = t + i * 256, oc = idx >> 4, p4 = (idx & 15) * 4;
        float4 v = *(float4*)&s_out[oc * 68 + p4];
        float4 xv = *(const float4*)&xp[(size_t)oc * HW + p4];
        v.x += xv.x; v.y += xv.y; v.z += xv.z; v.w += xv.w;
        *(float4*)&op[(size_t)oc * HW + p4] = v;
    }
}

// ---------- launch ----------
extern "C" void kernel_launch(void* const* d_in, const int* in_sizes, int n_in,
                              void* d_out, int out_size) {
    const float* x        = (const float*)d_in[0];
    const float* w_fc1    = (const float*)d_in[1];
    const float* ln1_w    = (const float*)d_in[2];
    const float* ln1_b    = (const float*)d_in[3];
    const float* w_fc2    = (const float*)d_in[4];
    const float* ln2_w    = (const float*)d_in[5];
    const float* ln2_b    = (const float*)d_in[6];
    const float* w_expand = (const float*)d_in[7];
    const float* w_shrink = (const float*)d_in[8];
    const float* grn_g    = (const float*)d_in[9];
    const float* grn_b    = (const float*)d_in[10];
    float* out = (float*)d_out;

    cudaFuncSetAttribute(k_expand, cudaFuncAttributeMaxDynamicSharedMemorySize, E_SMEM);
    cudaFuncSetAttribute(k_shrink, cudaFuncAttributeMaxDynamicSharedMemorySize, S_SMEM);

    k_wprep<<<256, 256>>>(w_expand, w_shrink);
    k_pool<<<Bn * Cn, 256>>>(x);
    k_fc<<<dim3(13, Bn), 256>>>(w_fc1, ln1_w, ln1_b, w_fc2);
    k_conv<<<Bn * Cn, 256>>>(x);
    k_expand<<<dim3(28, Bn), 256, E_SMEM>>>(ln2_w, ln2_b);
    k_grn<<<Bn, CEn>>>(grn_g);
    k_shrink<<<dim3(49, Bn), 256, S_SMEM>>>(grn_b, x, out);
}